// round 16
// baseline (speedup 1.0000x reference)
#include <cuda_runtime.h>
#include <cuda_bf16.h>
#include <math.h>
#include <cstdint>

#define Bc   4
#define Sc   2048
#define Dc   2048
#define LATc 512
#define NHc  16
#define NKVc 4
#define HDc  32
#define KVDc 128
#define Tc   (Bc * Sc)
#define GAINc 0.25f
#define EPSc  1e-6f
#define L2E  1.4426950408889634f

#define OFF_WQ 0
#define OFF_WK (LATc * Dc)
#define OFF_WV (OFF_WK + KVDc * Dc)
#define OFF_WO (OFF_WV + KVDc * Dc)
#define WTOT   (OFF_WO + Dc * LATc)

// prep kernel block partition
#define NB_X ((Tc * Dc / 4) / 256)         // 32768
#define NB_W ((WTOT / 4) / 256)            // 2560
#define NB_R ((Sc * 16) / 256)             // 128

// -------- scratch --------
__device__ float g_q [Tc * LATc];
__device__ float g_k [Tc * KVDc];
__device__ float g_v [Tc * KVDc];
__device__ float g_qc[Tc * LATc];
__device__ float g_kc[Tc * KVDc];
__device__ float g_o [Tc * LATc];
__device__ float2 g_rope[Sc * 16];
__device__ __nv_bfloat16 gb_xh[Tc * Dc];
__device__ __nv_bfloat16 gb_xl[Tc * Dc];
__device__ __nv_bfloat16 gb_wh[WTOT];
__device__ __nv_bfloat16 gb_wl[WTOT];
__device__ __nv_bfloat16 gb_ph[Tc * LATc];
__device__ __nv_bfloat16 gb_pl[Tc * LATc];
__device__ __nv_bfloat16 gb_qh[Tc * LATc];
__device__ __nv_bfloat16 gb_ql[Tc * LATc];
__device__ __nv_bfloat16 gb_kh[Tc * KVDc];
__device__ __nv_bfloat16 gb_kl[Tc * KVDc];
__device__ __nv_bfloat16 gb_vth[Tc * KVDc];
__device__ __nv_bfloat16 gb_vtl[Tc * KVDc];

// ---------------- helpers ----------------
__device__ __forceinline__ void mma_bf16(float* d, uint32_t a0, uint32_t a1,
                                         uint32_t a2, uint32_t a3,
                                         uint32_t b0, uint32_t b1) {
    asm volatile(
        "mma.sync.aligned.m16n8k16.row.col.f32.bf16.bf16.f32 "
        "{%0,%1,%2,%3}, {%4,%5,%6,%7}, {%8,%9}, {%0,%1,%2,%3};"
        : "+f"(d[0]), "+f"(d[1]), "+f"(d[2]), "+f"(d[3])
        : "r"(a0), "r"(a1), "r"(a2), "r"(a3), "r"(b0), "r"(b1));
}
#define LDSM4(R0, R1, R2, R3, addr) \
    asm volatile("ldmatrix.sync.aligned.m8n8.x4.shared.b16 {%0,%1,%2,%3}, [%4];" \
        : "=r"(R0), "=r"(R1), "=r"(R2), "=r"(R3) : "r"(addr))

__device__ __forceinline__ void fsplit_bf16(float x, __nv_bfloat16& h, __nv_bfloat16& l) {
    h = __float2bfloat16_rn(x);
    l = __float2bfloat16_rn(x - __bfloat162float(h));
}
__device__ __forceinline__ uint32_t smem_u32(const void* p) {
    uint32_t a;
    asm("{ .reg .u64 t; cvta.to.shared.u64 t, %1; cvt.u32.u64 %0, t; }" : "=r"(a) : "l"(p));
    return a;
}
#define CP_ASYNC16(dst, src) \
    asm volatile("cp.async.cg.shared.global [%0], [%1], 16;" :: "r"(dst), "l"(src))
#define CP_ASYNC8(dst, src) \
    asm volatile("cp.async.ca.shared.global [%0], [%1], 8;" :: "r"(dst), "l"(src))
#define CP_COMMIT() asm volatile("cp.async.commit_group;" ::: "memory")
#define CP_WAIT(n)  asm volatile("cp.async.wait_group %0;" :: "n"(n) : "memory")

__device__ __forceinline__ float fexp2(float t) {
    t = fmaxf(t, -126.f);
    float fi = floorf(t);
    float f = t - fi;
    int i = (int)fi;
    float p = 1.5403530393381609e-4f;
    p = fmaf(p, f, 1.3333558146428443e-3f);
    p = fmaf(p, f, 9.6181291076284772e-3f);
    p = fmaf(p, f, 5.5504108664821580e-2f);
    p = fmaf(p, f, 2.4022650695910072e-1f);
    p = fmaf(p, f, 6.9314718055994531e-1f);
    p = fmaf(p, f, 1.0f);
    return p * __int_as_float((i + 127) << 23);
}
// optimized: cvt.rn.bf16x2 packs two rn-rounded bf16 in one instr;
// bf16->f32 reconstruction is a pure bit shift. Bit-identical to the
// old 4x __float2bfloat16_rn version.
__device__ __forceinline__ void pack_split2(float a, float b, uint32_t& hi, uint32_t& lo) {
    uint32_t h;
    asm("cvt.rn.bf16x2.f32 %0, %1, %2;" : "=r"(h) : "f"(b), "f"(a));
    float ah = __uint_as_float(h << 16);
    float bh = __uint_as_float(h & 0xffff0000u);
    float la = a - ah;
    float lb = b - bh;
    uint32_t l;
    asm("cvt.rn.bf16x2.f32 %0, %1, %2;" : "=r"(l) : "f"(lb), "f"(la));
    hi = h; lo = l;
}

// ============================================================
// merged prep: x-split | weight-splits | rope tables (one launch)
// ============================================================
__global__ void __launch_bounds__(256) prep(
    __nv_bfloat16* __restrict__ xh, __nv_bfloat16* __restrict__ xl,
    const float* __restrict__ x,
    __nv_bfloat16* __restrict__ wh, __nv_bfloat16* __restrict__ wl,
    const float* __restrict__ wq, const float* __restrict__ wk,
    const float* __restrict__ wv, const float* __restrict__ wo,
    float2* __restrict__ rt)
{
    const int bid = blockIdx.x;
    const int tid = threadIdx.x;
    if (bid < NB_X) {
        int i = bid * 256 + tid;
        float4 v = ((const float4*)x)[i];
        __nv_bfloat16 h[4], l[4];
        fsplit_bf16(v.x, h[0], l[0]);
        fsplit_bf16(v.y, h[1], l[1]);
        fsplit_bf16(v.z, h[2], l[2]);
        fsplit_bf16(v.w, h[3], l[3]);
        ((uint2*)xh)[i] = *(uint2*)h;
        ((uint2*)xl)[i] = *(uint2*)l;
    } else if (bid < NB_X + NB_W) {
        int i = (bid - NB_X) * 256 + tid;
        const float* src;
        int base;
        if (i < OFF_WK / 4)      { src = wq; base = 0; }
        else if (i < OFF_WV / 4) { src = wk; base = OFF_WK / 4; }
        else if (i < OFF_WO / 4) { src = wv; base = OFF_WV / 4; }
        else                     { src = wo; base = OFF_WO / 4; }
        float4 v = ((const float4*)src)[i - base];
        __nv_bfloat16 h[4], l[4];
        fsplit_bf16(v.x, h[0], l[0]);
        fsplit_bf16(v.y, h[1], l[1]);
        fsplit_bf16(v.z, h[2], l[2]);
        fsplit_bf16(v.w, h[3], l[3]);
        ((uint2*)wh)[i] = *(uint2*)h;
        ((uint2*)wl)[i] = *(uint2*)l;
    } else {
        int idx = (bid - NB_X - NB_W) * 256 + tid;
        int s = idx >> 4, i = idx & 15;
        float fr = expf(-(float)i * 0.575646273248511f);
        float sn, cs;
        sincosf((float)s * fr, &sn, &cs);
        rt[idx] = make_float2(cs, sn);
    }
}

// ============================================================
// bf16 3-term split GEMM (R13 proven config)
// ============================================================
#define TSTRIDE 36
#define ABYTES  (128 * TSTRIDE * 4)
#define SBYTES  (4 * ABYTES)
#define GEMM_SMEM (3 * SBYTES)

__global__ void __launch_bounds__(256, 1) gemm_bf16(
    const __nv_bfloat16* __restrict__ Ah, const __nv_bfloat16* __restrict__ Al, int K,
    const __nv_bfloat16* __restrict__ Wh, const __nv_bfloat16* __restrict__ Wl,
    size_t off0, float* __restrict__ C0, int nx0, int N0,
    size_t off1, float* __restrict__ C1,
    size_t off2, float* __restrict__ C2)
{
    extern __shared__ char sm[];
    const int tid = threadIdx.x;
    const int wid = tid >> 5;
    const int lane = tid & 31;
    const int lr = lane >> 2;
    const int lc = lane & 3;
    const int wm = wid & 3;
    const int wn = wid >> 2;

    int bx = blockIdx.x;
    size_t woff;
    float* Cp;
    int N;
    if (bx < nx0)       { woff = off0; Cp = C0; N = N0; }
    else if (bx == nx0) { woff = off1; Cp = C1; N = 128; bx = 0; }
    else                { woff = off2; Cp = C2; N = 128; bx = 0; }
    const __nv_bfloat16* Bh = Wh + woff;
    const __nv_bfloat16* Bl = Wl + woff;
    const int m0 = blockIdx.y * 128;
    const int n0 = bx * 128;
    const int NC = K >> 6;

    const uint32_t smb = smem_u32(sm);
    int grow[4], gc16[4];
    uint32_t sdst[4];
#pragma unroll
    for (int j = 0; j < 4; j++) {
        int seg = tid + j * 256;
        grow[j] = seg >> 3;
        gc16[j] = seg & 7;
        sdst[j] = (uint32_t)(grow[j] * (TSTRIDE * 4) + gc16[j] * 16);
    }

    const int a_row = wm * 32 + (lane & 7) + ((lane >> 3) & 1) * 8;
    const uint32_t a_off = (uint32_t)(a_row * (TSTRIDE * 4) + ((lane >> 4) & 1) * 16);
    const int b_row = wn * 64 + (lane & 7) + ((lane >> 4) & 1) * 8;
    const uint32_t b_off = (uint32_t)(b_row * (TSTRIDE * 4) + ((lane >> 3) & 1) * 16);

    float acc[2][8][4];
#pragma unroll
    for (int mt = 0; mt < 2; mt++)
#pragma unroll
        for (int nt = 0; nt < 8; nt++)
#pragma unroll
            for (int c = 0; c < 4; c++) acc[mt][nt][c] = 0.f;

#pragma unroll
    for (int pc = 0; pc < 2; pc++) {
        const uint32_t so = smb + (uint32_t)pc * SBYTES;
        const int kt = pc << 6;
#pragma unroll
        for (int j = 0; j < 4; j++) {
            size_t ao = (size_t)(m0 + grow[j]) * K + kt + gc16[j] * 8;
            size_t bo = (size_t)(n0 + grow[j]) * K + kt + gc16[j] * 8;
            CP_ASYNC16(so + sdst[j],              Ah + ao);
            CP_ASYNC16(so + ABYTES + sdst[j],     Al + ao);
            CP_ASYNC16(so + 2 * ABYTES + sdst[j], Bh + bo);
            CP_ASYNC16(so + 3 * ABYTES + sdst[j], Bl + bo);
        }
        CP_COMMIT();
    }

    int bufi = 0;
    for (int i = 0; i < NC; i++) {
        if (i + 2 < NC) {
            int dsti = bufi + 2; if (dsti >= 3) dsti -= 3;
            const uint32_t so = smb + (uint32_t)dsti * SBYTES;
            const int kt = (i + 2) << 6;
#pragma unroll
            for (int j = 0; j < 4; j++) {
                size_t ao = (size_t)(m0 + grow[j]) * K + kt + gc16[j] * 8;
                size_t bo = (size_t)(n0 + grow[j]) * K + kt + gc16[j] * 8;
                CP_ASYNC16(so + sdst[j],              Ah + ao);
                CP_ASYNC16(so + ABYTES + sdst[j],     Al + ao);
                CP_ASYNC16(so + 2 * ABYTES + sdst[j], Bh + bo);
                CP_ASYNC16(so + 3 * ABYTES + sdst[j], Bl + bo);
            }
        }
        CP_COMMIT();
        CP_WAIT(2);
        __syncthreads();

        const uint32_t base = smb + (uint32_t)bufi * SBYTES;
        const uint32_t aAH = base + a_off;
        const uint32_t aAL = base + ABYTES + a_off;
        const uint32_t aBH = base + 2 * ABYTES + b_off;
        const uint32_t aBL = base + 3 * ABYTES + b_off;

#pragma unroll
        for (int ks = 0; ks < 4; ks++) {
            const uint32_t kb = (uint32_t)(ks * 32);
            uint32_t ah[2][4], al[2][4];
#pragma unroll
            for (int mt = 0; mt < 2; mt++) {
                const uint32_t mo = (uint32_t)(mt * 16 * TSTRIDE * 4);
                LDSM4(ah[mt][0], ah[mt][1], ah[mt][2], ah[mt][3], aAH + mo + kb);
                LDSM4(al[mt][0], al[mt][1], al[mt][2], al[mt][3], aAL + mo + kb);
            }
#pragma unroll
            for (int ntp = 0; ntp < 4; ntp++) {
                const uint32_t no = (uint32_t)(ntp * 16 * TSTRIDE * 4);
                uint32_t bh[4], bl[4];
                LDSM4(bh[0], bh[1], bh[2], bh[3], aBH + no + kb);
                LDSM4(bl[0], bl[1], bl[2], bl[3], aBL + no + kb);
#pragma unroll
                for (int t = 0; t < 2; t++)
#pragma unroll
                    for (int mt = 0; mt < 2; mt++)
                        mma_bf16(acc[mt][ntp * 2 + t],
                                 ah[mt][0], ah[mt][1], ah[mt][2], ah[mt][3],
                                 bh[2 * t], bh[2 * t + 1]);
#pragma unroll
                for (int t = 0; t < 2; t++)
#pragma unroll
                    for (int mt = 0; mt < 2; mt++)
                        mma_bf16(acc[mt][ntp * 2 + t],
                                 ah[mt][0], ah[mt][1], ah[mt][2], ah[mt][3],
                                 bl[2 * t], bl[2 * t + 1]);
#pragma unroll
                for (int t = 0; t < 2; t++)
#pragma unroll
                    for (int mt = 0; mt < 2; mt++)
                        mma_bf16(acc[mt][ntp * 2 + t],
                                 al[mt][0], al[mt][1], al[mt][2], al[mt][3],
                                 bh[2 * t], bh[2 * t + 1]);
            }
        }
        __syncthreads();
        if (++bufi == 3) bufi = 0;
    }

#pragma unroll
    for (int mt = 0; mt < 2; mt++) {
        const int r = m0 + wm * 32 + mt * 16 + lr;
#pragma unroll
        for (int nt = 0; nt < 8; nt++) {
            const int cN = n0 + wn * 64 + nt * 8 + 2 * lc;
            *(float2*)(Cp + (size_t)r * N + cN) =
                make_float2(acc[mt][nt][0], acc[mt][nt][1]);
            *(float2*)(Cp + (size_t)(r + 8) * N + cN) =
                make_float2(acc[mt][nt][2], acc[mt][nt][3]);
        }
    }
}

// ============================================================
// RMS kernels
// ============================================================
__device__ __forceinline__ void rms_row(float* row, const float* g, int C, int tid)
{
    float vr[4];
    int cnt = C >> 7;
    float ss = 0.f;
#pragma unroll 4
    for (int j = 0; j < cnt; j++) {
        int i = tid + j * 128;
        float v = row[i];
        vr[j] = v;
        ss += v * v;
    }
#pragma unroll
    for (int o = 16; o; o >>= 1) ss += __shfl_xor_sync(~0u, ss, o);
    __shared__ float ws[4];
    if ((tid & 31) == 0) ws[tid >> 5] = ss;
    __syncthreads();
    float tot = ws[0] + ws[1] + ws[2] + ws[3];
    float r = rsqrtf(tot / (float)C + EPSc);
#pragma unroll 4
    for (int j = 0; j < cnt; j++) {
        int i = tid + j * 128;
        row[i] = vr[j] * r * g[i];
    }
}

__global__ void __launch_bounds__(128) rms2(
    float* pa, const float* ga, int Ca,
    float* pb, const float* gb, int Cb)
{
    int t = blockIdx.x;
    if (t < Tc) rms_row(pa + (size_t)t * Ca, ga, Ca, threadIdx.x);
    else {
        t -= Tc;
        rms_row(pb + (size_t)t * Cb, gb, Cb, threadIdx.x);
    }
}

__global__ void __launch_bounds__(128) rms_split(
    const float* __restrict__ x, const float* __restrict__ g,
    __nv_bfloat16* __restrict__ hi, __nv_bfloat16* __restrict__ lo)
{
    const int t = blockIdx.x;
    const float* row = x + (size_t)t * LATc;
    const int tid = threadIdx.x;
    float vr[4];
    float ss = 0.f;
#pragma unroll
    for (int j = 0; j < 4; j++) {
        float v = row[tid + j * 128];
        vr[j] = v;
        ss += v * v;
    }
#pragma unroll
    for (int o = 16; o; o >>= 1) ss += __shfl_xor_sync(~0u, ss, o);
    __shared__ float ws[4];
    if ((tid & 31) == 0) ws[tid >> 5] = ss;
    __syncthreads();
    float tot = ws[0] + ws[1] + ws[2] + ws[3];
    float r = rsqrtf(tot / (float)LATc + EPSc);
#pragma unroll
    for (int j = 0; j < 4; j++) {
        int i = tid + j * 128;
        float y = vr[j] * r * g[i];
        __nv_bfloat16 h, l;
        fsplit_bf16(y, h, l);
        hi[(size_t)t * LATc + i] = h;
        lo[(size_t)t * LATc + i] = l;
    }
}

// ============================================================
// fused q/k pipeline (unchanged)
// ============================================================
__global__ void __launch_bounds__(128) fuse_qk(
    const float* __restrict__ pqc, const float* __restrict__ pkc,
    const float* __restrict__ pq_pre, const float* __restrict__ pk_pre,
    const float* __restrict__ g_conv, const float* __restrict__ g_kconv,
    const float* __restrict__ g_postq, const float* __restrict__ g_postk,
    const float* __restrict__ key_temp, const float2* __restrict__ rope,
    __nv_bfloat16* __restrict__ qsh, __nv_bfloat16* __restrict__ qsl,
    __nv_bfloat16* __restrict__ ksh, __nv_bfloat16* __restrict__ ksl)
{
    __shared__ float mean[32];
    __shared__ float ws[4];
    const int tid = threadIdx.x;
    const int lane = tid & 31;
    const int warp = tid >> 5;
    int t = blockIdx.x;
    const bool is_q = (t < Tc);
    if (!is_q) t -= Tc;
    const int s = t & (Sc - 1);
    const int C = is_q ? LATc : KVDc;
    const int cnt = C >> 7;

    if (tid < 32) {
        if (is_q) {
            const float* kr = pk_pre + (size_t)t * KVDc + tid;
            mean[tid] = GAINc * 0.25f * (kr[0] + kr[32] + kr[64] + kr[96]);
        } else {
            const float* qr = pq_pre + (size_t)t * LATc + tid;
            float sst = 0.f;
#pragma unroll
            for (int h = 0; h < 16; h++) sst += qr[h * 32];
            mean[tid] = GAINc * 0.0625f * sst;
        }
    }
    __syncthreads();

    const float* row = (is_q ? pqc : pkc) + (size_t)t * C;
    const float* g1 = is_q ? g_conv : g_kconv;
    const float* g2 = is_q ? g_postq : g_postk;

    float v[4];
    float ss = 0.f;
#pragma unroll 4
    for (int j = 0; j < cnt; j++) {
        float x = row[tid + j * 128];
        v[j] = x;
        ss += x * x;
    }
#pragma unroll
    for (int o = 16; o; o >>= 1) ss += __shfl_xor_sync(~0u, ss, o);
    if (lane == 0) ws[warp] = ss;
    __syncthreads();
    float r1 = rsqrtf((ws[0] + ws[1] + ws[2] + ws[3]) / (float)C + EPSc);

    float ss2 = 0.f;
#pragma unroll 4
    for (int j = 0; j < cnt; j++) {
        int i = tid + j * 128;
        float x = v[j] * r1 * g1[i] + mean[i & 31];
        v[j] = x;
        ss2 += x * x;
    }
#pragma unroll
    for (int o = 16; o; o >>= 1) ss2 += __shfl_xor_sync(~0u, ss2, o);
    __syncthreads();
    if (lane == 0) ws[warp] = ss2;
    __syncthreads();
    float r2 = rsqrtf((ws[0] + ws[1] + ws[2] + ws[3]) / (float)C + EPSc);

    const float kf = 5.656854249492380f * key_temp[0];
    const float2 cssn = rope[s * 16 + (lane >> 1)];
    const float sgn = (lane & 1) ? 1.f : -1.f;
    __nv_bfloat16* oh = is_q ? qsh : ksh;
    __nv_bfloat16* ol = is_q ? qsl : ksl;
#pragma unroll 4
    for (int j = 0; j < cnt; j++) {
        int i = tid + j * 128;
        float x = v[j] * r2 * g2[i];
        float hn = x * x;
#pragma unroll
        for (int o = 16; o; o >>= 1) hn += __shfl_xor_sync(~0u, hn, o);
        float n = fmaxf(sqrtf(hn), 1e-12f);
        float f = (is_q ? 1.0f : kf) / n;
        x *= f;
        float partner = __shfl_xor_sync(~0u, x, 1);
        float res = x * cssn.x + partner * cssn.y * sgn;
        __nv_bfloat16 h, l;
        fsplit_bf16(res, h, l);
        oh[(size_t)t * C + i] = h;
        ol[(size_t)t * C + i] = l;
    }
}

// ============================================================
// Grouped causal conv (merged q+k launch)
// ============================================================
__global__ void __launch_bounds__(256) conv_causal_qk(
    float* __restrict__ yq, const float* __restrict__ xq,
    const float* __restrict__ wq,
    float* __restrict__ yk, const float* __restrict__ xk,
    const float* __restrict__ wk)
{
    __shared__ float ws[96][33];
    __shared__ float xs[66][32];
    const int tid = threadIdx.x;
    const int t0 = blockIdx.x * 64;
    const int by = blockIdx.y;
    const bool is_q = (by < 16);
    const int base = (is_q ? by : by - 16) * 32;
    const int C = is_q ? LATc : KVDc;
    float* y = is_q ? yq : yk;
    const float* x = is_q ? xq : xk;
    const float* w = is_q ? wq : wk;
    const int s0 = t0 & (Sc - 1);

    for (int idx = tid; idx < 3072; idx += 256) {
        int co = idx / 96;
        int r = idx - co * 96;
        ws[r][co] = w[(size_t)(base + co) * 96 + r];
    }
    for (int idx = tid; idx < 66 * 32; idx += 256) {
        int row = idx >> 5;
        int ci = idx & 31;
        int srow = s0 - 2 + row;
        xs[row][ci] = (srow >= 0 && row < 66)
            ? x[(size_t)(t0 - 2 + row) * C + base + ci] : 0.f;
    }
    __syncthreads();

    const int co = tid & 31;
    const int tg = tid >> 5;
#pragma unroll
    for (int tk = 0; tk < 8; tk++) {
        const int tt = tg * 8 + tk;
        float acc = 0.f;
#pragma unroll 8
        for (int ci = 0; ci < 32; ci++) {
#pragma unroll
            for (int j = 0; j < 3; j++)
                acc += ws[ci * 3 + j][co] * xs[tt + j][ci];
        }
        y[(size_t)(t0 + tt) * C + base + co] = acc;
    }
}

// ============================================================
// fused v RMS + transpose + bf16 split (unchanged)
// ============================================================
__global__ void __launch_bounds__(256) vtrans_rms(
    const float* __restrict__ v, const float* __restrict__ g_kv,
    __nv_bfloat16* __restrict__ vh, __nv_bfloat16* __restrict__ vl)
{
    __shared__ float ts[32][132];
    __shared__ float rr[32];
    const int j0 = blockIdx.x * 32;
    const int b  = blockIdx.y;
    const int tid = threadIdx.x;
    const int ky = tid >> 3;
    const int c  = tid & 7;

    float ss = 0.f;
    const float* src = v + (size_t)(b * Sc + j0 + ky) * KVDc + c * 16;
#pragma unroll
    for (int q = 0; q < 4; q++) {
        float4 val = *(const float4*)(src + q * 4);
        int d0 = c * 16 + q * 4;
        ts[ky][d0 + 0] = val.x; ts[ky][d0 + 1] = val.y;
        ts[ky][d0 + 2] = val.z; ts[ky][d0 + 3] = val.w;
        ss += val.x * val.x + val.y * val.y + val.z * val.z + val.w * val.w;
    }
    ss += __shfl_xor_sync(~0u, ss, 1);
    ss += __shfl_xor_sync(~0u, ss, 2);
    ss += __shfl_xor_sync(~0u, ss, 4);
    if (c == 0) rr[ky] = rsqrtf(ss / (float)KVDc + EPSc);
    __syncthreads();

    const int d = tid >> 3;
    const int kp = (tid & 7) * 4;
#pragma unroll
    for (int kv = 0; kv < 4; kv++) {
        const float gg = g_kv[kv * 32 + d];
        __nv_bfloat16 hb[4], lb[4];
#pragma unroll
        for (int i = 0; i < 4; i++) {
            float val = ts[kp + i][kv * 32 + d] * rr[kp + i] * gg;
            fsplit_bf16(val, hb[i], lb[i]);
        }
        size_t dst = ((size_t)(b * 4 + kv) * 32 + d) * Sc + j0 + kp;
        *(uint2*)(vh + dst) = *(uint2*)hb;
        *(uint2*)(vl + dst) = *(uint2*)lb;
    }
}

// ============================================================
// mma flash attention: LDSM fragment loads, fixed-bound softmax
// ============================================================
__global__ void __launch_bounds__(256) flash_mma(
    float* __restrict__ o,
    const __nv_bfloat16* __restrict__ qh, const __nv_bfloat16* __restrict__ ql,
    const __nv_bfloat16* __restrict__ kh, const __nv_bfloat16* __restrict__ kl,
    const __nv_bfloat16* __restrict__ vth, const __nv_bfloat16* __restrict__ vtl,
    const float* __restrict__ key_temp)
{
    __shared__ __align__(16) uint32_t sK[2][2][64 * 20];
    __shared__ __align__(16) uint32_t sV[2][2][32 * 36];
    const int bh = blockIdx.y;
    const int b  = bh >> 4;
    const int h  = bh & 15;
    const int kv = h >> 2;
    const int sq0 = blockIdx.x * 128;
    const int tid = threadIdx.x;
    const int wq  = tid >> 5;
    const int lane = tid & 31;
    const int lr = lane >> 2;
    const int lc = lane & 3;
    const float M = 5.656854249492380f * fabsf(key_temp[0]) + 1e-3f;

    // ldmatrix per-lane offsets (b-operand mapping, validated in gemm)
    const uint32_t k_off = (uint32_t)(((lane & 7) + ((lane >> 4) & 1) * 8) * 80
                                      + ((lane >> 3) & 1) * 16);
    const uint32_t v_off = (uint32_t)(((lane & 7) + ((lane >> 4) & 1) * 8) * 144
                                      + ((lane >> 3) & 1) * 16);

    uint32_t qfh[2][4], qfl[2][4];
    {
        const int r0 = b * Sc + sq0 + wq * 16 + lr;
        const uint32_t* q0h = (const uint32_t*)(qh + (size_t)r0 * LATc + h * 32);
        const uint32_t* q8h = (const uint32_t*)(qh + (size_t)(r0 + 8) * LATc + h * 32);
        const uint32_t* q0l = (const uint32_t*)(ql + (size_t)r0 * LATc + h * 32);
        const uint32_t* q8l = (const uint32_t*)(ql + (size_t)(r0 + 8) * LATc + h * 32);
#pragma unroll
        for (int s = 0; s < 2; s++) {
            qfh[s][0] = q0h[8 * s + lc];
            qfh[s][1] = q8h[8 * s + lc];
            qfh[s][2] = q0h[8 * s + lc + 4];
            qfh[s][3] = q8h[8 * s + lc + 4];
            qfl[s][0] = q0l[8 * s + lc];
            qfl[s][1] = q8l[8 * s + lc];
            qfl[s][2] = q0l[8 * s + lc + 4];
            qfl[s][3] = q8l[8 * s + lc + 4];
        }
    }
    float oacc[4][4];
#pragma unroll
    for (int vn = 0; vn < 4; vn++)
#pragma unroll
        for (int c = 0; c < 4; c++) oacc[vn][c] = 0.f;
    float l0 = 0.f, l1 = 0.f;
    const int ntile = (sq0 >> 6) + 2;

#define LOAD_TILE(st, j0v) do { \
    const size_t gk = (size_t)(b * Sc + (j0v)); \
    for (int u = tid; u < 512; u += 256) { \
        int row = u >> 3, pp = u & 7; \
        CP_ASYNC8(smem_u32(&sK[st][0][row * 20 + pp * 2]), \
                  kh + (gk + row) * KVDc + kv * 32 + pp * 4); \
        CP_ASYNC8(smem_u32(&sK[st][1][row * 20 + pp * 2]), \
                  kl + (gk + row) * KVDc + kv * 32 + pp * 4); \
    } \
    { \
        int d = tid >> 3, q8 = tid & 7; \
        const size_t vs = ((size_t)(b * 4 + kv) * 32 + d) * Sc + (j0v) + q8 * 8; \
        CP_ASYNC16(smem_u32(&sV[st][0][d * 36 + q8 * 4]), vth + vs); \
        CP_ASYNC16(smem_u32(&sV[st][1][d * 36 + q8 * 4]), vtl + vs); \
    } \
} while (0)

    LOAD_TILE(0, 0);
    CP_COMMIT();

    for (int jt = 0; jt < ntile; jt++) {
        const int st = jt & 1;
        const int j0 = jt << 6;
        if (jt + 1 < ntile) {
            LOAD_TILE(st ^ 1, j0 + 64);
            CP_COMMIT();
            CP_WAIT(1);
        } else {
            CP_WAIT(0);
        }
        __syncthreads();

        const uint32_t aKH = smem_u32(&sK[st][0][0]) + k_off;
        const uint32_t aKL = smem_u32(&sK[st][1][0]) + k_off;
        const uint32_t aVH = smem_u32(&sV[st][0][0]) + v_off;
        const uint32_t aVL = smem_u32(&sV[st][1][0]) + v_off;

        // ---- QK^T via ldmatrix ----
        float sacc[8][4];
#pragma unroll
        for (int nt = 0; nt < 8; nt++)
#pragma unroll
            for (int c = 0; c < 4; c++) sacc[nt][c] = 0.f;
#pragma unroll
        for (int s = 0; s < 2; s++) {
#pragma unroll
            for (int ntp = 0; ntp < 4; ntp++) {
                const uint32_t no = (uint32_t)(ntp * 16 * 80) + (uint32_t)(s * 32);
                uint32_t bh4[4], bl4[4];
                LDSM4(bh4[0], bh4[1], bh4[2], bh4[3], aKH + no);
                LDSM4(bl4[0], bl4[1], bl4[2], bl4[3], aKL + no);
#pragma unroll
                for (int t = 0; t < 2; t++) {
                    const int nt = ntp * 2 + t;
                    mma_bf16(sacc[nt], qfh[s][0], qfh[s][1], qfh[s][2], qfh[s][3],
                             bh4[2 * t], bh4[2 * t + 1]);
                    mma_bf16(sacc[nt], qfh[s][0], qfh[s][1], qfh[s][2], qfh[s][3],
                             bl4[2 * t], bl4[2 * t + 1]);
                    mma_bf16(sacc[nt], qfl[s][0], qfl[s][1], qfl[s][2], qfl[s][3],
                             bh4[2 * t], bh4[2 * t + 1]);
                }
            }
        }
        const int r0 = sq0 + wq * 16 + lr;
        const int r1 = r0 + 8;
        const bool full = (j0 + 63) <= (sq0 + wq * 16);
        if (!full) {
#pragma unroll
            for (int nt = 0; nt < 8; nt++) {
                int kb = j0 + nt * 8 + 2 * lc;
                if (kb     > r0) sacc[nt][0] = -1e30f;
                if (kb + 1 > r0) sacc[nt][1] = -1e30f;
                if (kb     > r1) sacc[nt][2] = -1e30f;
                if (kb + 1 > r1) sacc[nt][3] = -1e30f;
            }
        }
        // ---- P = exp, pack, PV via ldmatrix ----
#pragma unroll
        for (int s2 = 0; s2 < 4; s2++) {
            float p0a = fexp2((sacc[2 * s2][0] - M) * L2E);
            float p0b = fexp2((sacc[2 * s2][1] - M) * L2E);
            float p8a = fexp2((sacc[2 * s2][2] - M) * L2E);
            float p8b = fexp2((sacc[2 * s2][3] - M) * L2E);
            float q0a = fexp2((sacc[2 * s2 + 1][0] - M) * L2E);
            float q0b = fexp2((sacc[2 * s2 + 1][1] - M) * L2E);
            float q8a = fexp2((sacc[2 * s2 + 1][2] - M) * L2E);
            float q8b = fexp2((sacc[2 * s2 + 1][3] - M) * L2E);
            l0 += p0a + p0b + q0a + q0b;
            l1 += p8a + p8b + q8a + q8b;
            uint32_t pha[4], pla[4];
            pack_split2(p0a, p0b, pha[0], pla[0]);
            pack_split2(p8a, p8b, pha[1], pla[1]);
            pack_split2(q0a, q0b, pha[2], pla[2]);
            pack_split2(q8a, q8b, pha[3], pla[3]);
#pragma unroll
            for (int vnp = 0; vnp < 2; vnp++) {
                const uint32_t vo = (uint32_t)(vnp * 16 * 144) + (uint32_t)(s2 * 32);
                uint32_t vh4[4], vl4[4];
                LDSM4(vh4[0], vh4[1], vh4[2], vh4[3], aVH + vo);
                LDSM4(vl4[0], vl4[1], vl4[2], vl4[3], aVL + vo);
#pragma unroll
                for (int t = 0; t < 2; t++) {
                    const int vn = vnp * 2 + t;
                    mma_bf16(oacc[vn], pha[0], pha[1], pha[2], pha[3],
                             vh4[2 * t], vh4[2 * t + 1]);
                    mma_bf16(oacc[vn], pha[0], pha[1], pha[2], pha[3],
                             vl4[2 * t], vl4[2 * t + 1]);
                    mma_bf16(oacc[vn], pla[0], pla[1], pla[2], pla[3],
                             vh4[2 * t], vh4[2 * t + 1]);
                }
            }
        }
        __syncthreads();
    }

    l0 += __shfl_xor_sync(~0u, l0, 1);
    l0 += __shfl_xor_sync(~0u, l0, 2);
    l1 += __shfl_xor_sync(~0u, l1, 1);
    l1 += __shfl_xor_sync(~0u, l1, 2);
    float i0 = 1.f / l0, i1 = 1.f / l1;
    const int gr0 = b * Sc + sq0 + wq * 16 + lr;
    float* o0 = o + (size_t)gr0 * LATc + h * 32;
    float* o8 = o + (size_t)(gr0 + 8) * LATc + h * 32;
#pragma unroll
    for (int vn = 0; vn < 4; vn++) {
        *(float2*)(o0 + vn * 8 + 2 * lc) = make_float2(oacc[vn][0] * i0, oacc[vn][1] * i0);
        *(float2*)(o8 + vn * 8 + 2 * lc) = make_float2(oacc[vn][2] * i1, oacc[vn][3] * i1);
    }
}

// ============================================================
// host launcher
// ============================================================
extern "C" void kernel_launch(void* const* d_in, const int* in_sizes, int n_in,
                              void* d_out, int out_size)
{
    const float* x        = (const float*)d_in[0];
    const float* w_q      = (const float*)d_in[1];
    const float* w_k      = (const float*)d_in[2];
    const float* w_v      = (const float*)d_in[3];
    const float* g_latent = (const float*)d_in[4];
    const float* g_kv     = (const float*)d_in[5];
    const float* conv_q_w = (const float*)d_in[6];
    const float* conv_k_w = (const float*)d_in[7];
    const float* g_conv   = (const float*)d_in[8];
    const float* g_kconv  = (const float*)d_in[9];
    const float* g_postq  = (const float*)d_in[10];
    const float* g_postk  = (const float*)d_in[11];
    const float* key_temp = (const float*)d_in[12];
    const float* g_preout = (const float*)d_in[13];
    const float* w_o      = (const float*)d_in[14];
    float* out = (float*)d_out;

    float *pq, *pk, *pv, *pqc, *pkc, *po;
    float2* prt;
    __nv_bfloat16 *pxh, *pxl, *pwh, *pwl, *pph, *ppl;
    __nv_bfloat16 *pqh, *pql2, *pkh, *pkl, *pvth, *pvtl;
    cudaGetSymbolAddress((void**)&pq,  g_q);
    cudaGetSymbolAddress((void**)&pk,  g_k);
    cudaGetSymbolAddress((void**)&pv,  g_v);
    cudaGetSymbolAddress((void**)&pqc, g_qc);
    cudaGetSymbolAddress((void**)&pkc, g_kc);
    cudaGetSymbolAddress((void**)&po,  g_o);
    cudaGetSymbolAddress((void**)&prt, g_rope);
    cudaGetSymbolAddress((void**)&pxh, gb_xh);
    cudaGetSymbolAddress((void**)&pxl, gb_xl);
    cudaGetSymbolAddress((void**)&pwh, gb_wh);
    cudaGetSymbolAddress((void**)&pwl, gb_wl);
    cudaGetSymbolAddress((void**)&pph, gb_ph);
    cudaGetSymbolAddress((void**)&ppl, gb_pl);
    cudaGetSymbolAddress((void**)&pqh, gb_qh);
    cudaGetSymbolAddress((void**)&pql2, gb_ql);
    cudaGetSymbolAddress((void**)&pkh, gb_kh);
    cudaGetSymbolAddress((void**)&pkl, gb_kl);
    cudaGetSymbolAddress((void**)&pvth, gb_vth);
    cudaGetSymbolAddress((void**)&pvtl, gb_vtl);

    cudaFuncSetAttribute(gemm_bf16, cudaFuncAttributeMaxDynamicSharedMemorySize, GEMM_SMEM);

    // 0) merged prep: x-split + weight-splits + rope tables
    prep<<<NB_X + NB_W + NB_R, 256>>>(pxh, pxl, x, pwh, pwl,
                                      w_q, w_k, w_v, w_o, prt);

    // 1) fused q/k/v projections
    gemm_bf16<<<dim3(6, Tc / 128), 256, GEMM_SMEM>>>(
        pxh, pxl, Dc, pwh, pwl,
        OFF_WQ, pq, 4, LATc, OFF_WK, pk, OFF_WV, pv);

    // 2) first RMS norms (q + k)
    rms2<<<2 * Tc, 128>>>(pq, g_latent, LATc, pk, g_kv, KVDc);

    // 3) causal grouped conv (merged q+k launch)
    conv_causal_qk<<<dim3(Tc / 64, 20), 256>>>(
        pqc, pq, conv_q_w, pkc, pk, conv_k_w);

    // 4) fused conv-RMS + mean-add + post-RMS + head-norm + RoPE + split
    fuse_qk<<<2 * Tc, 128>>>(pqc, pkc, pq, pk,
                             g_conv, g_kconv, g_postq, g_postk,
                             key_temp, prt, pqh, pql2, pkh, pkl);

    // 5) fused v RMS + transpose + split
    vtrans_rms<<<dim3(Sc / 32, Bc), 256>>>(pv, g_kv, pvth, pvtl);

    // 6) mma causal attention
    flash_mma<<<dim3(Sc / 128, Bc * NHc), 256>>>(
        po, pqh, pql2, pkh, pkl, pvth, pvtl, key_temp);

    // 7) pre-out RMS + split, then output projection
    rms_split<<<Tc, 128>>>(po, g_preout, pph, ppl);
    gemm_bf16<<<dim3(16, Tc / 128), 256, GEMM_SMEM>>>(
        pph, ppl, LATc, pwh, pwl,
        OFF_WO, out, 16, Dc, 0, nullptr, 0, nullptr);
}

// round 17
// speedup vs baseline: 1.5987x; 1.5987x over previous
#include <cuda_runtime.h>
#include <cuda_bf16.h>
#include <math.h>
#include <cstdint>

#define Bc   4
#define Sc   2048
#define Dc   2048
#define LATc 512
#define NHc  16
#define NKVc 4
#define HDc  32
#define KVDc 128
#define Tc   (Bc * Sc)
#define GAINc 0.25f
#define EPSc  1e-6f
#define L2E  1.4426950408889634f

#define OFF_WQ 0
#define OFF_WK (LATc * Dc)
#define OFF_WV (OFF_WK + KVDc * Dc)
#define OFF_WO (OFF_WV + KVDc * Dc)
#define WTOT   (OFF_WO + Dc * LATc)

// -------- scratch --------
__device__ float g_q [Tc * LATc];
__device__ float g_k [Tc * KVDc];
__device__ float g_v [Tc * KVDc];
__device__ float g_qc[Tc * LATc];
__device__ float g_kc[Tc * KVDc];
__device__ float g_o [Tc * LATc];
__device__ float2 g_rope[Sc * 16];
__device__ __nv_bfloat16 gb_xh[Tc * Dc];
__device__ __nv_bfloat16 gb_xl[Tc * Dc];
__device__ __nv_bfloat16 gb_wh[WTOT];
__device__ __nv_bfloat16 gb_wl[WTOT];
__device__ __nv_bfloat16 gb_ph[Tc * LATc];
__device__ __nv_bfloat16 gb_pl[Tc * LATc];
__device__ __nv_bfloat16 gb_qh[Tc * LATc];
__device__ __nv_bfloat16 gb_ql[Tc * LATc];
__device__ __nv_bfloat16 gb_kh[Tc * KVDc];
__device__ __nv_bfloat16 gb_kl[Tc * KVDc];
__device__ __nv_bfloat16 gb_vth[Tc * KVDc];
__device__ __nv_bfloat16 gb_vtl[Tc * KVDc];

// ---------------- helpers ----------------
__device__ __forceinline__ void mma_bf16(float* d, uint32_t a0, uint32_t a1,
                                         uint32_t a2, uint32_t a3,
                                         uint32_t b0, uint32_t b1) {
    asm volatile(
        "mma.sync.aligned.m16n8k16.row.col.f32.bf16.bf16.f32 "
        "{%0,%1,%2,%3}, {%4,%5,%6,%7}, {%8,%9}, {%0,%1,%2,%3};"
        : "+f"(d[0]), "+f"(d[1]), "+f"(d[2]), "+f"(d[3])
        : "r"(a0), "r"(a1), "r"(a2), "r"(a3), "r"(b0), "r"(b1));
}
#define LDSM4(R0, R1, R2, R3, addr) \
    asm volatile("ldmatrix.sync.aligned.m8n8.x4.shared.b16 {%0,%1,%2,%3}, [%4];" \
        : "=r"(R0), "=r"(R1), "=r"(R2), "=r"(R3) : "r"(addr))

__device__ __forceinline__ void fsplit_bf16(float x, __nv_bfloat16& h, __nv_bfloat16& l) {
    h = __float2bfloat16_rn(x);
    l = __float2bfloat16_rn(x - __bfloat162float(h));
}
__device__ __forceinline__ uint32_t smem_u32(const void* p) {
    uint32_t a;
    asm("{ .reg .u64 t; cvta.to.shared.u64 t, %1; cvt.u32.u64 %0, t; }" : "=r"(a) : "l"(p));
    return a;
}
#define CP_ASYNC16(dst, src) \
    asm volatile("cp.async.cg.shared.global [%0], [%1], 16;" :: "r"(dst), "l"(src))
#define CP_ASYNC8(dst, src) \
    asm volatile("cp.async.ca.shared.global [%0], [%1], 8;" :: "r"(dst), "l"(src))
#define CP_COMMIT() asm volatile("cp.async.commit_group;" ::: "memory")
#define CP_WAIT(n)  asm volatile("cp.async.wait_group %0;" :: "n"(n) : "memory")

__device__ __forceinline__ float fexp2(float t) {
    t = fmaxf(t, -126.f);
    float fi = floorf(t);
    float f = t - fi;
    int i = (int)fi;
    float p = 1.5403530393381609e-4f;
    p = fmaf(p, f, 1.3333558146428443e-3f);
    p = fmaf(p, f, 9.6181291076284772e-3f);
    p = fmaf(p, f, 5.5504108664821580e-2f);
    p = fmaf(p, f, 2.4022650695910072e-1f);
    p = fmaf(p, f, 6.9314718055994531e-1f);
    p = fmaf(p, f, 1.0f);
    return p * __int_as_float((i + 127) << 23);
}
__device__ __forceinline__ void pack_split2(float a, float b, uint32_t& hi, uint32_t& lo) {
    __nv_bfloat16 ha = __float2bfloat16_rn(a);
    __nv_bfloat16 hb = __float2bfloat16_rn(b);
    __nv_bfloat16 la = __float2bfloat16_rn(a - __bfloat162float(ha));
    __nv_bfloat16 lb = __float2bfloat16_rn(b - __bfloat162float(hb));
    __nv_bfloat162 H; H.x = ha; H.y = hb;
    __nv_bfloat162 L; L.x = la; L.y = lb;
    hi = *(uint32_t*)&H; lo = *(uint32_t*)&L;
}

// ============================================================
// rope tables
// ============================================================
__global__ void __launch_bounds__(256) rope_tab(float2* __restrict__ rt)
{
    int idx = blockIdx.x * 256 + threadIdx.x;
    if (idx >= Sc * 16) return;
    int s = idx >> 4, i = idx & 15;
    float fr = expf(-(float)i * 0.575646273248511f);
    float sn, cs;
    sincosf((float)s * fr, &sn, &cs);
    rt[idx] = make_float2(cs, sn);
}

// ============================================================
// split kernels
// ============================================================
__global__ void __launch_bounds__(256) split_arr(
    __nv_bfloat16* __restrict__ hi, __nv_bfloat16* __restrict__ lo,
    const float* __restrict__ src, int n4)
{
    int i = blockIdx.x * 256 + threadIdx.x;
    if (i >= n4) return;
    float4 v = ((const float4*)src)[i];
    __nv_bfloat16 h[4], l[4];
    fsplit_bf16(v.x, h[0], l[0]);
    fsplit_bf16(v.y, h[1], l[1]);
    fsplit_bf16(v.z, h[2], l[2]);
    fsplit_bf16(v.w, h[3], l[3]);
    ((uint2*)hi)[i] = *(uint2*)h;
    ((uint2*)lo)[i] = *(uint2*)l;
}

__global__ void __launch_bounds__(256) split_w4(
    __nv_bfloat16* __restrict__ hi, __nv_bfloat16* __restrict__ lo,
    const float* __restrict__ wq, const float* __restrict__ wk,
    const float* __restrict__ wv, const float* __restrict__ wo)
{
    int i = blockIdx.x * 256 + threadIdx.x;
    const float* src;
    int base;
    if (i < OFF_WK / 4)      { src = wq; base = 0; }
    else if (i < OFF_WV / 4) { src = wk; base = OFF_WK / 4; }
    else if (i < OFF_WO / 4) { src = wv; base = OFF_WV / 4; }
    else if (i < WTOT / 4)   { src = wo; base = OFF_WO / 4; }
    else return;
    float4 v = ((const float4*)src)[i - base];
    __nv_bfloat16 h[4], l[4];
    fsplit_bf16(v.x, h[0], l[0]);
    fsplit_bf16(v.y, h[1], l[1]);
    fsplit_bf16(v.z, h[2], l[2]);
    fsplit_bf16(v.w, h[3], l[3]);
    ((uint2*)hi)[i] = *(uint2*)h;
    ((uint2*)lo)[i] = *(uint2*)l;
}

// ============================================================
// bf16 3-term split GEMM (R13 proven config)
// ============================================================
#define TSTRIDE 36
#define ABYTES  (128 * TSTRIDE * 4)
#define SBYTES  (4 * ABYTES)
#define GEMM_SMEM (3 * SBYTES)

__global__ void __launch_bounds__(256, 1) gemm_bf16(
    const __nv_bfloat16* __restrict__ Ah, const __nv_bfloat16* __restrict__ Al, int K,
    const __nv_bfloat16* __restrict__ Wh, const __nv_bfloat16* __restrict__ Wl,
    size_t off0, float* __restrict__ C0, int nx0, int N0,
    size_t off1, float* __restrict__ C1,
    size_t off2, float* __restrict__ C2)
{
    extern __shared__ char sm[];
    const int tid = threadIdx.x;
    const int wid = tid >> 5;
    const int lane = tid & 31;
    const int lr = lane >> 2;
    const int lc = lane & 3;
    const int wm = wid & 3;
    const int wn = wid >> 2;

    int bx = blockIdx.x;
    size_t woff;
    float* Cp;
    int N;
    if (bx < nx0)       { woff = off0; Cp = C0; N = N0; }
    else if (bx == nx0) { woff = off1; Cp = C1; N = 128; bx = 0; }
    else                { woff = off2; Cp = C2; N = 128; bx = 0; }
    const __nv_bfloat16* Bh = Wh + woff;
    const __nv_bfloat16* Bl = Wl + woff;
    const int m0 = blockIdx.y * 128;
    const int n0 = bx * 128;
    const int NC = K >> 6;

    const uint32_t smb = smem_u32(sm);
    int grow[4], gc16[4];
    uint32_t sdst[4];
#pragma unroll
    for (int j = 0; j < 4; j++) {
        int seg = tid + j * 256;
        grow[j] = seg >> 3;
        gc16[j] = seg & 7;
        sdst[j] = (uint32_t)(grow[j] * (TSTRIDE * 4) + gc16[j] * 16);
    }

    const int a_row = wm * 32 + (lane & 7) + ((lane >> 3) & 1) * 8;
    const uint32_t a_off = (uint32_t)(a_row * (TSTRIDE * 4) + ((lane >> 4) & 1) * 16);
    const int b_row = wn * 64 + (lane & 7) + ((lane >> 4) & 1) * 8;
    const uint32_t b_off = (uint32_t)(b_row * (TSTRIDE * 4) + ((lane >> 3) & 1) * 16);

    float acc[2][8][4];
#pragma unroll
    for (int mt = 0; mt < 2; mt++)
#pragma unroll
        for (int nt = 0; nt < 8; nt++)
#pragma unroll
            for (int c = 0; c < 4; c++) acc[mt][nt][c] = 0.f;

#pragma unroll
    for (int pc = 0; pc < 2; pc++) {
        const uint32_t so = smb + (uint32_t)pc * SBYTES;
        const int kt = pc << 6;
#pragma unroll
        for (int j = 0; j < 4; j++) {
            size_t ao = (size_t)(m0 + grow[j]) * K + kt + gc16[j] * 8;
            size_t bo = (size_t)(n0 + grow[j]) * K + kt + gc16[j] * 8;
            CP_ASYNC16(so + sdst[j],              Ah + ao);
            CP_ASYNC16(so + ABYTES + sdst[j],     Al + ao);
            CP_ASYNC16(so + 2 * ABYTES + sdst[j], Bh + bo);
            CP_ASYNC16(so + 3 * ABYTES + sdst[j], Bl + bo);
        }
        CP_COMMIT();
    }

    int bufi = 0;
    for (int i = 0; i < NC; i++) {
        if (i + 2 < NC) {
            int dsti = bufi + 2; if (dsti >= 3) dsti -= 3;
            const uint32_t so = smb + (uint32_t)dsti * SBYTES;
            const int kt = (i + 2) << 6;
#pragma unroll
            for (int j = 0; j < 4; j++) {
                size_t ao = (size_t)(m0 + grow[j]) * K + kt + gc16[j] * 8;
                size_t bo = (size_t)(n0 + grow[j]) * K + kt + gc16[j] * 8;
                CP_ASYNC16(so + sdst[j],              Ah + ao);
                CP_ASYNC16(so + ABYTES + sdst[j],     Al + ao);
                CP_ASYNC16(so + 2 * ABYTES + sdst[j], Bh + bo);
                CP_ASYNC16(so + 3 * ABYTES + sdst[j], Bl + bo);
            }
        }
        CP_COMMIT();
        CP_WAIT(2);
        __syncthreads();

        const uint32_t base = smb + (uint32_t)bufi * SBYTES;
        const uint32_t aAH = base + a_off;
        const uint32_t aAL = base + ABYTES + a_off;
        const uint32_t aBH = base + 2 * ABYTES + b_off;
        const uint32_t aBL = base + 3 * ABYTES + b_off;

#pragma unroll
        for (int ks = 0; ks < 4; ks++) {
            const uint32_t kb = (uint32_t)(ks * 32);
            uint32_t ah[2][4], al[2][4];
#pragma unroll
            for (int mt = 0; mt < 2; mt++) {
                const uint32_t mo = (uint32_t)(mt * 16 * TSTRIDE * 4);
                LDSM4(ah[mt][0], ah[mt][1], ah[mt][2], ah[mt][3], aAH + mo + kb);
                LDSM4(al[mt][0], al[mt][1], al[mt][2], al[mt][3], aAL + mo + kb);
            }
#pragma unroll
            for (int ntp = 0; ntp < 4; ntp++) {
                const uint32_t no = (uint32_t)(ntp * 16 * TSTRIDE * 4);
                uint32_t bh[4], bl[4];
                LDSM4(bh[0], bh[1], bh[2], bh[3], aBH + no + kb);
                LDSM4(bl[0], bl[1], bl[2], bl[3], aBL + no + kb);
#pragma unroll
                for (int t = 0; t < 2; t++)
#pragma unroll
                    for (int mt = 0; mt < 2; mt++)
                        mma_bf16(acc[mt][ntp * 2 + t],
                                 ah[mt][0], ah[mt][1], ah[mt][2], ah[mt][3],
                                 bh[2 * t], bh[2 * t + 1]);
#pragma unroll
                for (int t = 0; t < 2; t++)
#pragma unroll
                    for (int mt = 0; mt < 2; mt++)
                        mma_bf16(acc[mt][ntp * 2 + t],
                                 ah[mt][0], ah[mt][1], ah[mt][2], ah[mt][3],
                                 bl[2 * t], bl[2 * t + 1]);
#pragma unroll
                for (int t = 0; t < 2; t++)
#pragma unroll
                    for (int mt = 0; mt < 2; mt++)
                        mma_bf16(acc[mt][ntp * 2 + t],
                                 al[mt][0], al[mt][1], al[mt][2], al[mt][3],
                                 bh[2 * t], bh[2 * t + 1]);
            }
        }
        __syncthreads();
        if (++bufi == 3) bufi = 0;
    }

#pragma unroll
    for (int mt = 0; mt < 2; mt++) {
        const int r = m0 + wm * 32 + mt * 16 + lr;
#pragma unroll
        for (int nt = 0; nt < 8; nt++) {
            const int cN = n0 + wn * 64 + nt * 8 + 2 * lc;
            *(float2*)(Cp + (size_t)r * N + cN) =
                make_float2(acc[mt][nt][0], acc[mt][nt][1]);
            *(float2*)(Cp + (size_t)(r + 8) * N + cN) =
                make_float2(acc[mt][nt][2], acc[mt][nt][3]);
        }
    }
}

// ============================================================
// RMS kernels
// ============================================================
__device__ __forceinline__ void rms_row(float* row, const float* g, int C, int tid)
{
    float vr[4];
    int cnt = C >> 7;
    float ss = 0.f;
#pragma unroll 4
    for (int j = 0; j < cnt; j++) {
        int i = tid + j * 128;
        float v = row[i];
        vr[j] = v;
        ss += v * v;
    }
#pragma unroll
    for (int o = 16; o; o >>= 1) ss += __shfl_xor_sync(~0u, ss, o);
    __shared__ float ws[4];
    if ((tid & 31) == 0) ws[tid >> 5] = ss;
    __syncthreads();
    float tot = ws[0] + ws[1] + ws[2] + ws[3];
    float r = rsqrtf(tot / (float)C + EPSc);
#pragma unroll 4
    for (int j = 0; j < cnt; j++) {
        int i = tid + j * 128;
        row[i] = vr[j] * r * g[i];
    }
}

__global__ void __launch_bounds__(128) rms2(
    float* pa, const float* ga, int Ca,
    float* pb, const float* gb, int Cb)
{
    int t = blockIdx.x;
    if (t < Tc) rms_row(pa + (size_t)t * Ca, ga, Ca, threadIdx.x);
    else {
        t -= Tc;
        rms_row(pb + (size_t)t * Cb, gb, Cb, threadIdx.x);
    }
}

__global__ void __launch_bounds__(128) rms_split(
    const float* __restrict__ x, const float* __restrict__ g,
    __nv_bfloat16* __restrict__ hi, __nv_bfloat16* __restrict__ lo)
{
    const int t = blockIdx.x;
    const float* row = x + (size_t)t * LATc;
    const int tid = threadIdx.x;
    float vr[4];
    float ss = 0.f;
#pragma unroll
    for (int j = 0; j < 4; j++) {
        float v = row[tid + j * 128];
        vr[j] = v;
        ss += v * v;
    }
#pragma unroll
    for (int o = 16; o; o >>= 1) ss += __shfl_xor_sync(~0u, ss, o);
    __shared__ float ws[4];
    if ((tid & 31) == 0) ws[tid >> 5] = ss;
    __syncthreads();
    float tot = ws[0] + ws[1] + ws[2] + ws[3];
    float r = rsqrtf(tot / (float)LATc + EPSc);
#pragma unroll
    for (int j = 0; j < 4; j++) {
        int i = tid + j * 128;
        float y = vr[j] * r * g[i];
        __nv_bfloat16 h, l;
        fsplit_bf16(y, h, l);
        hi[(size_t)t * LATc + i] = h;
        lo[(size_t)t * LATc + i] = l;
    }
}

// ============================================================
// fused q/k pipeline (unchanged from R15)
// ============================================================
__global__ void __launch_bounds__(128) fuse_qk(
    const float* __restrict__ pqc, const float* __restrict__ pkc,
    const float* __restrict__ pq_pre, const float* __restrict__ pk_pre,
    const float* __restrict__ g_conv, const float* __restrict__ g_kconv,
    const float* __restrict__ g_postq, const float* __restrict__ g_postk,
    const float* __restrict__ key_temp, const float2* __restrict__ rope,
    __nv_bfloat16* __restrict__ qsh, __nv_bfloat16* __restrict__ qsl,
    __nv_bfloat16* __restrict__ ksh, __nv_bfloat16* __restrict__ ksl)
{
    __shared__ float mean[32];
    __shared__ float ws[4];
    const int tid = threadIdx.x;
    const int lane = tid & 31;
    const int warp = tid >> 5;
    int t = blockIdx.x;
    const bool is_q = (t < Tc);
    if (!is_q) t -= Tc;
    const int s = t & (Sc - 1);
    const int C = is_q ? LATc : KVDc;
    const int cnt = C >> 7;

    if (tid < 32) {
        if (is_q) {
            const float* kr = pk_pre + (size_t)t * KVDc + tid;
            mean[tid] = GAINc * 0.25f * (kr[0] + kr[32] + kr[64] + kr[96]);
        } else {
            const float* qr = pq_pre + (size_t)t * LATc + tid;
            float sst = 0.f;
#pragma unroll
            for (int h = 0; h < 16; h++) sst += qr[h * 32];
            mean[tid] = GAINc * 0.0625f * sst;
        }
    }
    __syncthreads();

    const float* row = (is_q ? pqc : pkc) + (size_t)t * C;
    const float* g1 = is_q ? g_conv : g_kconv;
    const float* g2 = is_q ? g_postq : g_postk;

    float v[4];
    float ss = 0.f;
#pragma unroll 4
    for (int j = 0; j < cnt; j++) {
        float x = row[tid + j * 128];
        v[j] = x;
        ss += x * x;
    }
#pragma unroll
    for (int o = 16; o; o >>= 1) ss += __shfl_xor_sync(~0u, ss, o);
    if (lane == 0) ws[warp] = ss;
    __syncthreads();
    float r1 = rsqrtf((ws[0] + ws[1] + ws[2] + ws[3]) / (float)C + EPSc);

    float ss2 = 0.f;
#pragma unroll 4
    for (int j = 0; j < cnt; j++) {
        int i = tid + j * 128;
        float x = v[j] * r1 * g1[i] + mean[i & 31];
        v[j] = x;
        ss2 += x * x;
    }
#pragma unroll
    for (int o = 16; o; o >>= 1) ss2 += __shfl_xor_sync(~0u, ss2, o);
    __syncthreads();
    if (lane == 0) ws[warp] = ss2;
    __syncthreads();
    float r2 = rsqrtf((ws[0] + ws[1] + ws[2] + ws[3]) / (float)C + EPSc);

    const float kf = 5.656854249492380f * key_temp[0];
    const float2 cssn = rope[s * 16 + (lane >> 1)];
    const float sgn = (lane & 1) ? 1.f : -1.f;
    __nv_bfloat16* oh = is_q ? qsh : ksh;
    __nv_bfloat16* ol = is_q ? qsl : ksl;
#pragma unroll 4
    for (int j = 0; j < cnt; j++) {
        int i = tid + j * 128;
        float x = v[j] * r2 * g2[i];
        float hn = x * x;
#pragma unroll
        for (int o = 16; o; o >>= 1) hn += __shfl_xor_sync(~0u, hn, o);
        float n = fmaxf(sqrtf(hn), 1e-12f);
        float f = (is_q ? 1.0f : kf) / n;
        x *= f;
        float partner = __shfl_xor_sync(~0u, x, 1);
        float res = x * cssn.x + partner * cssn.y * sgn;
        __nv_bfloat16 h, l;
        fsplit_bf16(res, h, l);
        oh[(size_t)t * C + i] = h;
        ol[(size_t)t * C + i] = l;
    }
}

// ============================================================
// Grouped causal conv (merged q+k launch), register-blocked
// inner loop: per ci, hoist 3 weights + 10 broadcast x values,
// then 24 fma from registers. Same accumulation order as before.
// ============================================================
__global__ void __launch_bounds__(256) conv_causal_qk(
    float* __restrict__ yq, const float* __restrict__ xq,
    const float* __restrict__ wq,
    float* __restrict__ yk, const float* __restrict__ xk,
    const float* __restrict__ wk)
{
    __shared__ float ws[96][33];
    __shared__ float xs[66][32];
    const int tid = threadIdx.x;
    const int t0 = blockIdx.x * 64;
    const int by = blockIdx.y;
    const bool is_q = (by < 16);
    const int base = (is_q ? by : by - 16) * 32;
    const int C = is_q ? LATc : KVDc;
    float* y = is_q ? yq : yk;
    const float* x = is_q ? xq : xk;
    const float* w = is_q ? wq : wk;
    const int s0 = t0 & (Sc - 1);

    for (int idx = tid; idx < 3072; idx += 256) {
        int co = idx / 96;
        int r = idx - co * 96;
        ws[r][co] = w[(size_t)(base + co) * 96 + r];
    }
    for (int idx = tid; idx < 66 * 32; idx += 256) {
        int row = idx >> 5;
        int ci = idx & 31;
        int srow = s0 - 2 + row;
        xs[row][ci] = (srow >= 0 && row < 66)
            ? x[(size_t)(t0 - 2 + row) * C + base + ci] : 0.f;
    }
    __syncthreads();

    const int co = tid & 31;
    const int tg = tid >> 5;
    float acc[8];
#pragma unroll
    for (int tk = 0; tk < 8; tk++) acc[tk] = 0.f;

#pragma unroll 4
    for (int ci = 0; ci < 32; ci++) {
        const float w0 = ws[ci * 3 + 0][co];
        const float w1 = ws[ci * 3 + 1][co];
        const float w2 = ws[ci * 3 + 2][co];
        float xv[10];
#pragma unroll
        for (int r = 0; r < 10; r++) xv[r] = xs[tg * 8 + r][ci];
#pragma unroll
        for (int tk = 0; tk < 8; tk++) {
            // same fma order (j = 0,1,2) as the original loop
            acc[tk] = fmaf(w0, xv[tk], acc[tk]);
            acc[tk] = fmaf(w1, xv[tk + 1], acc[tk]);
            acc[tk] = fmaf(w2, xv[tk + 2], acc[tk]);
        }
    }
#pragma unroll
    for (int tk = 0; tk < 8; tk++)
        y[(size_t)(t0 + tg * 8 + tk) * C + base + co] = acc[tk];
}

// ============================================================
// fused v RMS + transpose + bf16 split (unchanged)
// ============================================================
__global__ void __launch_bounds__(256) vtrans_rms(
    const float* __restrict__ v, const float* __restrict__ g_kv,
    __nv_bfloat16* __restrict__ vh, __nv_bfloat16* __restrict__ vl)
{
    __shared__ float ts[32][132];
    __shared__ float rr[32];
    const int j0 = blockIdx.x * 32;
    const int b  = blockIdx.y;
    const int tid = threadIdx.x;
    const int ky = tid >> 3;
    const int c  = tid & 7;

    float ss = 0.f;
    const float* src = v + (size_t)(b * Sc + j0 + ky) * KVDc + c * 16;
#pragma unroll
    for (int q = 0; q < 4; q++) {
        float4 val = *(const float4*)(src + q * 4);
        int d0 = c * 16 + q * 4;
        ts[ky][d0 + 0] = val.x; ts[ky][d0 + 1] = val.y;
        ts[ky][d0 + 2] = val.z; ts[ky][d0 + 3] = val.w;
        ss += val.x * val.x + val.y * val.y + val.z * val.z + val.w * val.w;
    }
    ss += __shfl_xor_sync(~0u, ss, 1);
    ss += __shfl_xor_sync(~0u, ss, 2);
    ss += __shfl_xor_sync(~0u, ss, 4);
    if (c == 0) rr[ky] = rsqrtf(ss / (float)KVDc + EPSc);
    __syncthreads();

    const int d = tid >> 3;
    const int kp = (tid & 7) * 4;
#pragma unroll
    for (int kv = 0; kv < 4; kv++) {
        const float gg = g_kv[kv * 32 + d];
        __nv_bfloat16 hb[4], lb[4];
#pragma unroll
        for (int i = 0; i < 4; i++) {
            float val = ts[kp + i][kv * 32 + d] * rr[kp + i] * gg;
            fsplit_bf16(val, hb[i], lb[i]);
        }
        size_t dst = ((size_t)(b * 4 + kv) * 32 + d) * Sc + j0 + kp;
        *(uint2*)(vh + dst) = *(uint2*)hb;
        *(uint2*)(vl + dst) = *(uint2*)lb;
    }
}

// ============================================================
// mma flash attention (R15 scalar-LDS version, proven)
// ============================================================
__global__ void __launch_bounds__(256) flash_mma(
    float* __restrict__ o,
    const __nv_bfloat16* __restrict__ qh, const __nv_bfloat16* __restrict__ ql,
    const __nv_bfloat16* __restrict__ kh, const __nv_bfloat16* __restrict__ kl,
    const __nv_bfloat16* __restrict__ vth, const __nv_bfloat16* __restrict__ vtl,
    const float* __restrict__ key_temp)
{
    __shared__ uint32_t sK[2][2][64 * 20];
    __shared__ uint32_t sV[2][2][32 * 36];
    const int bh = blockIdx.y;
    const int b  = bh >> 4;
    const int h  = bh & 15;
    const int kv = h >> 2;
    const int sq0 = blockIdx.x * 128;
    const int tid = threadIdx.x;
    const int wq  = tid >> 5;
    const int lane = tid & 31;
    const int lr = lane >> 2;
    const int lc = lane & 3;
    const float M = 5.656854249492380f * fabsf(key_temp[0]) + 1e-3f;

    uint32_t qfh[2][4], qfl[2][4];
    {
        const int r0 = b * Sc + sq0 + wq * 16 + lr;
        const uint32_t* q0h = (const uint32_t*)(qh + (size_t)r0 * LATc + h * 32);
        const uint32_t* q8h = (const uint32_t*)(qh + (size_t)(r0 + 8) * LATc + h * 32);
        const uint32_t* q0l = (const uint32_t*)(ql + (size_t)r0 * LATc + h * 32);
        const uint32_t* q8l = (const uint32_t*)(ql + (size_t)(r0 + 8) * LATc + h * 32);
#pragma unroll
        for (int s = 0; s < 2; s++) {
            qfh[s][0] = q0h[8 * s + lc];
            qfh[s][1] = q8h[8 * s + lc];
            qfh[s][2] = q0h[8 * s + lc + 4];
            qfh[s][3] = q8h[8 * s + lc + 4];
            qfl[s][0] = q0l[8 * s + lc];
            qfl[s][1] = q8l[8 * s + lc];
            qfl[s][2] = q0l[8 * s + lc + 4];
            qfl[s][3] = q8l[8 * s + lc + 4];
        }
    }
    float oacc[4][4];
#pragma unroll
    for (int vn = 0; vn < 4; vn++)
#pragma unroll
        for (int c = 0; c < 4; c++) oacc[vn][c] = 0.f;
    float l0 = 0.f, l1 = 0.f;
    const int ntile = (sq0 >> 6) + 2;

#define LOAD_TILE(st, j0v) do { \
    const size_t gk = (size_t)(b * Sc + (j0v)); \
    for (int u = tid; u < 512; u += 256) { \
        int row = u >> 3, pp = u & 7; \
        CP_ASYNC8(smem_u32(&sK[st][0][row * 20 + pp * 2]), \
                  kh + (gk + row) * KVDc + kv * 32 + pp * 4); \
        CP_ASYNC8(smem_u32(&sK[st][1][row * 20 + pp * 2]), \
                  kl + (gk + row) * KVDc + kv * 32 + pp * 4); \
    } \
    { \
        int d = tid >> 3, q8 = tid & 7; \
        const size_t vs = ((size_t)(b * 4 + kv) * 32 + d) * Sc + (j0v) + q8 * 8; \
        CP_ASYNC16(smem_u32(&sV[st][0][d * 36 + q8 * 4]), vth + vs); \
        CP_ASYNC16(smem_u32(&sV[st][1][d * 36 + q8 * 4]), vtl + vs); \
    } \
} while (0)

    LOAD_TILE(0, 0);
    CP_COMMIT();

    for (int jt = 0; jt < ntile; jt++) {
        const int st = jt & 1;
        const int j0 = jt << 6;
        if (jt + 1 < ntile) {
            LOAD_TILE(st ^ 1, j0 + 64);
            CP_COMMIT();
            CP_WAIT(1);
        } else {
            CP_WAIT(0);
        }
        __syncthreads();

        float sacc[8][4];
#pragma unroll
        for (int nt = 0; nt < 8; nt++)
#pragma unroll
            for (int c = 0; c < 4; c++) sacc[nt][c] = 0.f;
#pragma unroll
        for (int s = 0; s < 2; s++) {
#pragma unroll
            for (int nt = 0; nt < 8; nt++) {
                const uint32_t* Kr0 = &sK[st][0][(nt * 8 + lr) * 20 + 8 * s + lc];
                const uint32_t* Kr1 = &sK[st][1][(nt * 8 + lr) * 20 + 8 * s + lc];
                uint32_t b0 = Kr0[0], b1 = Kr0[4];
                uint32_t c0 = Kr1[0], c1 = Kr1[4];
                mma_bf16(sacc[nt], qfh[s][0], qfh[s][1], qfh[s][2], qfh[s][3], b0, b1);
                mma_bf16(sacc[nt], qfh[s][0], qfh[s][1], qfh[s][2], qfh[s][3], c0, c1);
                mma_bf16(sacc[nt], qfl[s][0], qfl[s][1], qfl[s][2], qfl[s][3], b0, b1);
            }
        }
        const int r0 = sq0 + wq * 16 + lr;
        const int r1 = r0 + 8;
        const bool full = (j0 + 63) <= (sq0 + wq * 16);
        if (!full) {
#pragma unroll
            for (int nt = 0; nt < 8; nt++) {
                int kb = j0 + nt * 8 + 2 * lc;
                if (kb     > r0) sacc[nt][0] = -1e30f;
                if (kb + 1 > r0) sacc[nt][1] = -1e30f;
                if (kb     > r1) sacc[nt][2] = -1e30f;
                if (kb + 1 > r1) sacc[nt][3] = -1e30f;
            }
        }
#pragma unroll
        for (int s2 = 0; s2 < 4; s2++) {
            float p0a = fexp2((sacc[2 * s2][0] - M) * L2E);
            float p0b = fexp2((sacc[2 * s2][1] - M) * L2E);
            float p8a = fexp2((sacc[2 * s2][2] - M) * L2E);
            float p8b = fexp2((sacc[2 * s2][3] - M) * L2E);
            float q0a = fexp2((sacc[2 * s2 + 1][0] - M) * L2E);
            float q0b = fexp2((sacc[2 * s2 + 1][1] - M) * L2E);
            float q8a = fexp2((sacc[2 * s2 + 1][2] - M) * L2E);
            float q8b = fexp2((sacc[2 * s2 + 1][3] - M) * L2E);
            l0 += p0a + p0b + q0a + q0b;
            l1 += p8a + p8b + q8a + q8b;
            uint32_t pha[4], pla[4];
            pack_split2(p0a, p0b, pha[0], pla[0]);
            pack_split2(p8a, p8b, pha[1], pla[1]);
            pack_split2(q0a, q0b, pha[2], pla[2]);
            pack_split2(q8a, q8b, pha[3], pla[3]);
#pragma unroll
            for (int vn = 0; vn < 4; vn++) {
                const uint32_t* Vr0 = &sV[st][0][(vn * 8 + lr) * 36 + 8 * s2 + lc];
                const uint32_t* Vr1 = &sV[st][1][(vn * 8 + lr) * 36 + 8 * s2 + lc];
                uint32_t b0 = Vr0[0], b1 = Vr0[4];
                uint32_t c0 = Vr1[0], c1 = Vr1[4];
                mma_bf16(oacc[vn], pha[0], pha[1], pha[2], pha[3], b0, b1);
                mma_bf16(oacc[vn], pha[0], pha[1], pha[2], pha[3], c0, c1);
                mma_bf16(oacc[vn], pla[0], pla[1], pla[2], pla[3], b0, b1);
            }
        }
        __syncthreads();
    }

    l0 += __shfl_xor_sync(~0u, l0, 1);
    l0 += __shfl_xor_sync(~0u, l0, 2);
    l1 += __shfl_xor_sync(~0u, l1, 1);
    l1 += __shfl_xor_sync(~0u, l1, 2);
    float i0 = 1.f / l0, i1 = 1.f / l1;
    const int gr0 = b * Sc + sq0 + wq * 16 + lr;
    float* o0 = o + (size_t)gr0 * LATc + h * 32;
    float* o8 = o + (size_t)(gr0 + 8) * LATc + h * 32;
#pragma unroll
    for (int vn = 0; vn < 4; vn++) {
        *(float2*)(o0 + vn * 8 + 2 * lc) = make_float2(oacc[vn][0] * i0, oacc[vn][1] * i0);
        *(float2*)(o8 + vn * 8 + 2 * lc) = make_float2(oacc[vn][2] * i1, oacc[vn][3] * i1);
    }
}

// ============================================================
// host launcher
// ============================================================
extern "C" void kernel_launch(void* const* d_in, const int* in_sizes, int n_in,
                              void* d_out, int out_size)
{
    const float* x        = (const float*)d_in[0];
    const float* w_q      = (const float*)d_in[1];
    const float* w_k      = (const float*)d_in[2];
    const float* w_v      = (const float*)d_in[3];
    const float* g_latent = (const float*)d_in[4];
    const float* g_kv     = (const float*)d_in[5];
    const float* conv_q_w = (const float*)d_in[6];
    const float* conv_k_w = (const float*)d_in[7];
    const float* g_conv   = (const float*)d_in[8];
    const float* g_kconv  = (const float*)d_in[9];
    const float* g_postq  = (const float*)d_in[10];
    const float* g_postk  = (const float*)d_in[11];
    const float* key_temp = (const float*)d_in[12];
    const float* g_preout = (const float*)d_in[13];
    const float* w_o      = (const float*)d_in[14];
    float* out = (float*)d_out;

    float *pq, *pk, *pv, *pqc, *pkc, *po;
    float2* prt;
    __nv_bfloat16 *pxh, *pxl, *pwh, *pwl, *pph, *ppl;
    __nv_bfloat16 *pqh, *pql2, *pkh, *pkl, *pvth, *pvtl;
    cudaGetSymbolAddress((void**)&pq,  g_q);
    cudaGetSymbolAddress((void**)&pk,  g_k);
    cudaGetSymbolAddress((void**)&pv,  g_v);
    cudaGetSymbolAddress((void**)&pqc, g_qc);
    cudaGetSymbolAddress((void**)&pkc, g_kc);
    cudaGetSymbolAddress((void**)&po,  g_o);
    cudaGetSymbolAddress((void**)&prt, g_rope);
    cudaGetSymbolAddress((void**)&pxh, gb_xh);
    cudaGetSymbolAddress((void**)&pxl, gb_xl);
    cudaGetSymbolAddress((void**)&pwh, gb_wh);
    cudaGetSymbolAddress((void**)&pwl, gb_wl);
    cudaGetSymbolAddress((void**)&pph, gb_ph);
    cudaGetSymbolAddress((void**)&ppl, gb_pl);
    cudaGetSymbolAddress((void**)&pqh, gb_qh);
    cudaGetSymbolAddress((void**)&pql2, gb_ql);
    cudaGetSymbolAddress((void**)&pkh, gb_kh);
    cudaGetSymbolAddress((void**)&pkl, gb_kl);
    cudaGetSymbolAddress((void**)&pvth, gb_vth);
    cudaGetSymbolAddress((void**)&pvtl, gb_vtl);

    cudaFuncSetAttribute(gemm_bf16, cudaFuncAttributeMaxDynamicSharedMemorySize, GEMM_SMEM);

    // 0) rope tables + pre-splits
    rope_tab<<<(Sc * 16 + 255) / 256, 256>>>(prt);
    split_arr<<<(Tc * Dc / 4 + 255) / 256, 256>>>(pxh, pxl, x, Tc * Dc / 4);
    split_w4<<<(WTOT / 4 + 255) / 256, 256>>>(pwh, pwl, w_q, w_k, w_v, w_o);

    // 1) fused q/k/v projections
    gemm_bf16<<<dim3(6, Tc / 128), 256, GEMM_SMEM>>>(
        pxh, pxl, Dc, pwh, pwl,
        OFF_WQ, pq, 4, LATc, OFF_WK, pk, OFF_WV, pv);

    // 2) first RMS norms (q + k)
    rms2<<<2 * Tc, 128>>>(pq, g_latent, LATc, pk, g_kv, KVDc);

    // 3) causal grouped conv (merged q+k launch, register-blocked)
    conv_causal_qk<<<dim3(Tc / 64, 20), 256>>>(
        pqc, pq, conv_q_w, pkc, pk, conv_k_w);

    // 4) fused conv-RMS + mean-add + post-RMS + head-norm + RoPE + split
    fuse_qk<<<2 * Tc, 128>>>(pqc, pkc, pq, pk,
                             g_conv, g_kconv, g_postq, g_postk,
                             key_temp, prt, pqh, pql2, pkh, pkl);

    // 5) fused v RMS + transpose + split
    vtrans_rms<<<dim3(Sc / 32, Bc), 256>>>(pv, g_kv, pvth, pvtl);

    // 6) mma causal attention
    flash_mma<<<dim3(Sc / 128, Bc * NHc), 256>>>(
        po, pqh, pql2, pkh, pkl, pvth, pvtl, key_temp);

    // 7) pre-out RMS + split, then output projection
    rms_split<<<Tc, 128>>>(po, g_preout, pph, ppl);
    gemm_bf16<<<dim3(16, Tc / 128), 256, GEMM_SMEM>>>(
        pph, ppl, LATc, pwh, pwl,
        OFF_WO, out, 16, Dc, 0, nullptr, 0, nullptr);
}